// round 2
// baseline (speedup 1.0000x reference)
#include <cuda_runtime.h>

// Problem constants (fixed by reference setup_inputs)
#define B_   4096
#define NI   1024
#define NH   4096
#define NO   512
#define MAXDEV 1024

// ---------------------------------------------------------------------------
// Static scratch (no allocations allowed in kernel_launch)
// ---------------------------------------------------------------------------
__device__ float g_cur1[(size_t)B_ * NH];   // 64 MB: cur1 = x@W1^T + b1
__device__ float g_G[(size_t)B_ * NO];      //  8 MB: G = cur1@W2^T
__device__ int   g_devCount;                // # of mem1 elements that could reset
__device__ int   g_devB[MAXDEV];
__device__ int   g_devH[MAXDEV];
__device__ float g_devV[MAXDEV];
__device__ float g_devD[MAXDEV * 10];       // exact mem1 deviation per step

// s_t = sum_{i=0}^{t-1} 0.5^i  (exactly representable dyadic values)
#define S_LIST {1.0f, 1.5f, 1.75f, 1.875f, 1.9375f, 1.96875f, 1.984375f, \
                1.9921875f, 1.99609375f, 1.998046875f}

// ---------------------------------------------------------------------------
// C[M,N] = A[M,K] @ B[N,K]^T (+ bias[n]); optional detection of C > 7.5
// Tiles: 128x128x8, 256 threads, 8x8 per thread, register-prefetched gmem.
// All of M, N divisible by 128 and K divisible by 8 (true for this problem).
// ---------------------------------------------------------------------------
template <bool BIAS, bool DETECT>
__global__ __launch_bounds__(256, 2)
void gemm_nt(const float* __restrict__ A, const float* __restrict__ B,
             const float* __restrict__ bias, float* __restrict__ C,
             int M, int N, int K)
{
    __shared__ float As[8][128];
    __shared__ float Bs[8][128];

    const int tid  = threadIdx.x;
    const int tx   = tid & 15;     // 0..15  -> 8 output cols
    const int ty   = tid >> 4;     // 0..15  -> 8 output rows
    const int brow = blockIdx.y * 128;
    const int bcol = blockIdx.x * 128;

    // gmem load mapping: 256 threads x 1 float4 covers a 128x8 tile
    const int lr = tid >> 1;            // tile row 0..127
    const int lk = (tid & 1) * 4;       // k offset 0 or 4

    const float* Ap = A + (size_t)(brow + lr) * K + lk;
    const float* Bp = B + (size_t)(bcol + lr) * K + lk;

    float4 a4 = *(const float4*)Ap;
    float4 b4 = *(const float4*)Bp;

    float acc[8][8];
#pragma unroll
    for (int i = 0; i < 8; i++)
#pragma unroll
        for (int j = 0; j < 8; j++) acc[i][j] = 0.0f;

    const int nk = K / 8;
    for (int kt = 0; kt < nk; ++kt) {
        As[lk + 0][lr] = a4.x; As[lk + 1][lr] = a4.y;
        As[lk + 2][lr] = a4.z; As[lk + 3][lr] = a4.w;
        Bs[lk + 0][lr] = b4.x; Bs[lk + 1][lr] = b4.y;
        Bs[lk + 2][lr] = b4.z; Bs[lk + 3][lr] = b4.w;
        __syncthreads();

        if (kt + 1 < nk) {  // prefetch next k-panel into registers
            a4 = *(const float4*)(Ap + (size_t)(kt + 1) * 8);
            b4 = *(const float4*)(Bp + (size_t)(kt + 1) * 8);
        }

#pragma unroll
        for (int k = 0; k < 8; k++) {
            float ar[8], br[8];
            *(float4*)&ar[0] = *(const float4*)&As[k][ty * 8];
            *(float4*)&ar[4] = *(const float4*)&As[k][ty * 8 + 4];
            *(float4*)&br[0] = *(const float4*)&Bs[k][tx * 8];
            *(float4*)&br[4] = *(const float4*)&Bs[k][tx * 8 + 4];
#pragma unroll
            for (int i = 0; i < 8; i++)
#pragma unroll
                for (int j = 0; j < 8; j++)
                    acc[i][j] = fmaf(ar[i], br[j], acc[i][j]);
        }
        __syncthreads();
    }

    // epilogue
#pragma unroll
    for (int i = 0; i < 8; i++) {
        const int row = brow + ty * 8 + i;
        float* Crow = C + (size_t)row * N + bcol + tx * 8;
#pragma unroll
        for (int j = 0; j < 8; j++) {
            float c = acc[i][j];
            if (BIAS) c += bias[bcol + tx * 8 + j];
            Crow[j] = c;
            if (DETECT) {
                // mem1 can only reset if s_t * cur1 > 15 for some t<=9,
                // i.e. cur1 > 15/1.99609375 = 7.5147. Use 7.5 (conservative).
                if (c > 7.5f) {
                    int p = atomicAdd(&g_devCount, 1);
                    if (p < MAXDEV) {
                        g_devB[p] = row;
                        g_devH[p] = bcol + tx * 8 + j;
                        g_devV[p] = c;
                    }
                }
            }
        }
    }
}

// ---------------------------------------------------------------------------
// reset the deviation counter (graph replays must be deterministic)
// ---------------------------------------------------------------------------
__global__ void k_reset()
{
    if (threadIdx.x == 0) g_devCount = 0;
}

// ---------------------------------------------------------------------------
// For each flagged mem1 element: run the exact reference recursion and record
// d_t = mem1_exact(t) - s_t * cur1  for t = 1..10.
// ---------------------------------------------------------------------------
__global__ void k_fixup()
{
    const int i = blockIdx.x * blockDim.x + threadIdx.x;
    int cnt = g_devCount;
    if (cnt > MAXDEV) cnt = MAXDEV;
    if (i >= cnt) return;

    const float S[10] = S_LIST;
    const float c = g_devV[i];
    float m = 0.0f;
#pragma unroll
    for (int t = 0; t < 10; t++) {
        const float r = (m > 15.0f) ? 15.0f : 0.0f;
        m = 0.5f * m + c - r;
        g_devD[i * 10 + t] = m - S[t] * c;
    }
}

// ---------------------------------------------------------------------------
// mem2 recursion, fully elementwise:
//   cur2_t = s_t * G + b2 (+ sparse corrections), mem2 = 0.5*mem2 + cur2 - 10*H
// Writes spk2 then mem2 into d_out.
// ---------------------------------------------------------------------------
__global__ void k_out(const float* __restrict__ G, const float* __restrict__ b2,
                      const float* __restrict__ W2, float* __restrict__ out)
{
    const int idx = blockIdx.x * blockDim.x + threadIdx.x;
    if (idx >= B_ * NO) return;
    const int b = idx / NO;
    const int n = idx - b * NO;

    const float g    = G[idx];
    const float bias = b2[n];

    float fix[10];
#pragma unroll
    for (int t = 0; t < 10; t++) fix[t] = 0.0f;

    int cnt = g_devCount;
    if (cnt > 0) {                       // expected never taken
        if (cnt > MAXDEV) cnt = MAXDEV;
        for (int e = 0; e < cnt; e++) {
            if (g_devB[e] == b) {
                const float w = W2[(size_t)n * NH + g_devH[e]];
#pragma unroll
                for (int t = 0; t < 10; t++)
                    fix[t] = fmaf(g_devD[e * 10 + t], w, fix[t]);
            }
        }
    }

    const float S[10] = S_LIST;
    float m2 = 0.0f;
#pragma unroll
    for (int t = 0; t < 10; t++) {
        const float r  = (m2 > 10.0f) ? 10.0f : 0.0f;
        const float c2 = S[t] * g + bias + fix[t];
        m2 = 0.5f * m2 + c2 - r;
    }

    out[idx] = (m2 > 10.0f) ? 1.0f : 0.0f;      // spk2
    out[(size_t)B_ * NO + idx] = m2;            // mem2
}

// ---------------------------------------------------------------------------
// launch
// ---------------------------------------------------------------------------
extern "C" void kernel_launch(void* const* d_in, const int* in_sizes, int n_in,
                              void* d_out, int out_size)
{
    const float* x  = (const float*)d_in[0];
    const float* W1 = (const float*)d_in[1];
    const float* b1 = (const float*)d_in[2];
    const float* W2 = (const float*)d_in[3];
    const float* b2 = (const float*)d_in[4];
    float* out = (float*)d_out;

    float* cur1 = nullptr;
    float* G    = nullptr;
    cudaGetSymbolAddress((void**)&cur1, g_cur1);
    cudaGetSymbolAddress((void**)&G, g_G);

    k_reset<<<1, 32>>>();

    // cur1 = x @ W1^T + b1, with reset-possibility detection
    {
        dim3 grid(NH / 128, B_ / 128);
        gemm_nt<true, true><<<grid, 256>>>(x, W1, b1, cur1, B_, NH, NI);
    }

    k_fixup<<<MAXDEV / 128, 128>>>();

    // G = cur1 @ W2^T
    {
        dim3 grid(NO / 128, B_ / 128);
        gemm_nt<false, false><<<grid, 256>>>(cur1, W2, nullptr, G, B_, NO, NH);
    }

    // mem2 scan + outputs
    k_out<<<(B_ * NO) / 256, 256>>>(G, b2, W2, out);
}

// round 10
// speedup vs baseline: 2.3262x; 2.3262x over previous
#include <cuda_runtime.h>
#include <cuda_fp16.h>
#include <cstdint>

// Problem constants (fixed by reference setup_inputs)
#define B_   4096
#define NI   1024
#define NH   4096
#define NO   512
#define MAXDEV 1024
#define SPLITK 4
#define LSCALE 2048.0f           // Ootomo residual up-scale (exact power of 2)
#define INV_LSCALE (1.0f / 2048.0f)

// ---------------------------------------------------------------------------
// Static scratch as float4 arrays (16B alignment for cp.async), cast to half*.
// Weight pre-scales (exact powers of 2) keep hi terms O(1):
//   W1*32 (W1~N(0,1/1024)), W2*64 (W2~N(0,1/4096)).
// All lo arrays store 2048*(v - fp16(v)) so they are NORMAL fp16 (~0.25|v|),
// immune to tensor-core FTZ of subnormal inputs (the round-8 failure).
// ---------------------------------------------------------------------------
__device__ float4 g_xh0[(size_t)B_ * NI / 8],  g_xh1[(size_t)B_ * NI / 8];
__device__ float4 g_w1h0[(size_t)NH * NI / 8], g_w1h1[(size_t)NH * NI / 8];
__device__ float4 g_w2h0[(size_t)NO * NH / 8], g_w2h1[(size_t)NO * NH / 8];
__device__ float4 g_c1h0[(size_t)B_ * NH / 8], g_c1h1[(size_t)B_ * NH / 8];
__device__ float4 g_Gpv[(size_t)SPLITK * B_ * NO / 4];
__device__ int    g_devCount;
__device__ int    g_devB[MAXDEV];
__device__ int    g_devH[MAXDEV];
__device__ float  g_devV[MAXDEV];
__device__ float  g_devD[MAXDEV * 10];

// s_t = sum_{i=0}^{t-1} 0.5^i (exact dyadic values)
#define S_LIST {1.0f, 1.5f, 1.75f, 1.875f, 1.9375f, 1.96875f, 1.984375f, \
                1.9921875f, 1.99609375f, 1.998046875f}

// ---------------------------------------------------------------------------
// PTX helpers (base sm_100 target: fp16 mma.sync + cp.async only)
// ---------------------------------------------------------------------------
__device__ __forceinline__ uint32_t smem_u32(const void* p) {
    uint32_t a;
    asm("{ .reg .u64 t; cvta.to.shared.u64 t, %1; cvt.u32.u64 %0, t; }" : "=r"(a) : "l"(p));
    return a;
}
__device__ __forceinline__ void cp16(uint32_t dst, const void* src) {
    asm volatile("cp.async.cg.shared.global [%0], [%1], 16;" :: "r"(dst), "l"(src) : "memory");
}
#define CP_COMMIT() asm volatile("cp.async.commit_group;" ::: "memory")
#define CP_WAIT0()  asm volatile("cp.async.wait_group 0;" ::: "memory")

// D(16x8,f32) += A(16x16,f16) @ B(16x8,f16)
__device__ __forceinline__ void mma16(float* d, const uint32_t* a, const uint32_t* b) {
    asm volatile(
        "mma.sync.aligned.m16n8k16.row.col.f32.f16.f16.f32 "
        "{%0,%1,%2,%3}, {%4,%5,%6,%7}, {%8,%9}, {%0,%1,%2,%3};"
        : "+f"(d[0]), "+f"(d[1]), "+f"(d[2]), "+f"(d[3])
        : "r"(a[0]), "r"(a[1]), "r"(a[2]), "r"(a[3]), "r"(b[0]), "r"(b[1]));
}

// ---------------------------------------------------------------------------
// Elementwise split with pre-scale:
//   v = f*scale;  h0 = fp16(v);  h1 = fp16(2048*(v - h0))   (always normal)
// ---------------------------------------------------------------------------
__global__ void k_split(const float* __restrict__ s, __half* __restrict__ h0,
                        __half* __restrict__ h1, float scale, int n4)
{
    int i = blockIdx.x * blockDim.x + threadIdx.x;
    if (i >= n4) return;
    float4 v = ((const float4*)s)[i];
    v.x *= scale; v.y *= scale; v.z *= scale; v.w *= scale;
    __half a0 = __float2half_rn(v.x), a1 = __float2half_rn(v.y);
    __half a2 = __float2half_rn(v.z), a3 = __float2half_rn(v.w);
    __half b0 = __float2half_rn(LSCALE * (v.x - __half2float(a0)));
    __half b1 = __float2half_rn(LSCALE * (v.y - __half2float(a1)));
    __half b2 = __float2half_rn(LSCALE * (v.z - __half2float(a2)));
    __half b3 = __float2half_rn(LSCALE * (v.w - __half2float(a3)));
    ((__half2*)h0)[2 * i]     = __halves2half2(a0, a1);
    ((__half2*)h0)[2 * i + 1] = __halves2half2(a2, a3);
    ((__half2*)h1)[2 * i]     = __halves2half2(b0, b1);
    ((__half2*)h1)[2 * i + 1] = __halves2half2(b2, b3);
}

// ---------------------------------------------------------------------------
// fp16 split-GEMM with separate correction accumulator (Ootomo):
//   acc  += Ah@Bh          (main)
//   cor  += Ah@Bl' + Al'@Bh  (corrections at 2048x scale)
//   C = (acc + cor/2048) * inv
// CTA tile 128x128, BK=32, 8 warps (warp tile 32x64), 2-stage cp.async.
// Smem rows: 32 halfs padded to 20 words (stride%32==20 => conflict-free LDS32).
// EPI=0: +bias, reset-detect, write fp16 split (hi, 2048*lo) of result
// EPI=1: write fp32 partial at blockIdx.z K-slice
// ---------------------------------------------------------------------------
#define BM 128
#define BN 128
#define BK 32
#define SW 20                          // words per row (16 data + 4 pad)
#define A_WORDS (BM * SW)              // 2560
#define B_WORDS (BN * SW)              // 2560
#define STGW (2 * A_WORDS + 2 * B_WORDS)  // 10240 words = 40960 B
#define SM_BYTES (2 * STGW * 4)        // 81920

template <int EPI>
__global__ __launch_bounds__(256, 1)
void gemm_h2(const __half* __restrict__ A0, const __half* __restrict__ A1,
             const __half* __restrict__ B0, const __half* __restrict__ B1,
             const float* __restrict__ bias,
             __half* __restrict__ O0, __half* __restrict__ O1,
             float* __restrict__ Of,
             int lda, int ldb, int ldc, int Klen, float inv)
{
    extern __shared__ uint32_t smw[];
    const int tid  = threadIdx.x;
    const int wid  = tid >> 5;
    const int lane = tid & 31;
    const int gr   = lane >> 2;   // fragment row group
    const int tg   = lane & 3;    // fragment col group
    const int warpRow = (wid >> 1) * 32;   // 4 warp-rows of 32
    const int warpCol = (wid & 1) * 64;    // 2 warp-cols of 64
    const int row0 = blockIdx.y * BM;
    const int col0 = blockIdx.x * BN;
    const int k0   = blockIdx.z * Klen;

    float acc[2][8][4];
    float cor[2][8][4];
#pragma unroll
    for (int mf = 0; mf < 2; mf++)
#pragma unroll
        for (int nf = 0; nf < 8; nf++)
#pragma unroll
            for (int j = 0; j < 4; j++) { acc[mf][nf][j] = 0.0f; cor[mf][nf][j] = 0.0f; }

    // stage loader: K-tile t -> buffer s (each row = 32 halfs = 4x cp16)
    auto load_stage = [&](int t, int s) {
        const int kof = k0 + t * BK;
        const uint32_t sa = smem_u32(smw + s * STGW);
        for (int q = tid; q < BM * 4; q += 256) {
            const int r = q >> 2, ch = q & 3;
            const size_t go = (size_t)(row0 + r) * lda + kof + ch * 8;
            const uint32_t so = sa + (uint32_t)(r * SW + ch * 4) * 4;
            cp16(so, A0 + go);
            cp16(so + A_WORDS * 4, A1 + go);
        }
        for (int q = tid; q < BN * 4; q += 256) {
            const int r = q >> 2, ch = q & 3;
            const size_t go = (size_t)(col0 + r) * ldb + kof + ch * 8;
            const uint32_t so = sa + (uint32_t)(2 * A_WORDS + r * SW + ch * 4) * 4;
            cp16(so, B0 + go);
            cp16(so + B_WORDS * 4, B1 + go);
        }
        CP_COMMIT();
    };

    const int T = Klen / BK;
    load_stage(0, 0);

    for (int t = 0; t < T; t++) {
        CP_WAIT0();            // stage t resident
        __syncthreads();
        if (t + 1 < T) load_stage(t + 1, (t + 1) & 1);   // overlaps compute below

        const uint32_t* Ah = smw + (t & 1) * STGW;
        const uint32_t* Al = Ah + A_WORDS;
        const uint32_t* Bh = Ah + 2 * A_WORDS;
        const uint32_t* Bl = Ah + 3 * A_WORDS;

#pragma unroll
        for (int sl = 0; sl < 2; sl++) {     // two k16 slabs per BK=32
            const int kb = sl * 8;           // word offset within row
            uint32_t ah[2][4], al[2][4];
#pragma unroll
            for (int mf = 0; mf < 2; mf++) {
                const int r  = warpRow + mf * 16 + gr;
                const int w0 = r * SW + kb + tg;
                const int w1 = w0 + 8 * SW;
                ah[mf][0] = Ah[w0]; ah[mf][1] = Ah[w1];
                ah[mf][2] = Ah[w0 + 4]; ah[mf][3] = Ah[w1 + 4];
                al[mf][0] = Al[w0]; al[mf][1] = Al[w1];
                al[mf][2] = Al[w0 + 4]; al[mf][3] = Al[w1 + 4];
            }
#pragma unroll
            for (int nf = 0; nf < 8; nf++) {
                const int wb = (warpCol + nf * 8 + gr) * SW + kb + tg;
                uint32_t bh[2], bl[2];
                bh[0] = Bh[wb]; bh[1] = Bh[wb + 4];
                bl[0] = Bl[wb]; bl[1] = Bl[wb + 4];
#pragma unroll
                for (int mf = 0; mf < 2; mf++) {
                    mma16(acc[mf][nf], ah[mf], bh);   // hi*hi   -> main
                    mma16(cor[mf][nf], ah[mf], bl);   // hi*lo'  -> corr (2048x)
                    mma16(cor[mf][nf], al[mf], bh);   // lo'*hi  -> corr (2048x)
                }
            }
        }
        __syncthreads();
    }

    // epilogue: c0,c1 -> row gr, cols 2tg..2tg+1; c2,c3 -> row gr+8
    float* outf = Of;
    if (EPI == 1) outf += (size_t)blockIdx.z * B_ * NO;

#pragma unroll
    for (int mf = 0; mf < 2; mf++)
#pragma unroll
        for (int h = 0; h < 2; h++) {
            const int grow = row0 + warpRow + mf * 16 + gr + h * 8;
#pragma unroll
            for (int nf = 0; nf < 8; nf++) {
                const int gcol = col0 + warpCol + nf * 8 + tg * 2;
                float v0 = fmaf(cor[mf][nf][h * 2 + 0], INV_LSCALE, acc[mf][nf][h * 2 + 0]) * inv;
                float v1 = fmaf(cor[mf][nf][h * 2 + 1], INV_LSCALE, acc[mf][nf][h * 2 + 1]) * inv;
                if (EPI == 0) {
                    v0 += __ldg(&bias[gcol]);
                    v1 += __ldg(&bias[gcol + 1]);
                    // mem1 can only reset if cur1 > 15/1.996 = 7.51; use 7.5
                    if (v0 > 7.5f) {
                        int p = atomicAdd(&g_devCount, 1);
                        if (p < MAXDEV) { g_devB[p] = grow; g_devH[p] = gcol; g_devV[p] = v0; }
                    }
                    if (v1 > 7.5f) {
                        int p = atomicAdd(&g_devCount, 1);
                        if (p < MAXDEV) { g_devB[p] = grow; g_devH[p] = gcol + 1; g_devV[p] = v1; }
                    }
                    __half h00 = __float2half_rn(v0), h01 = __float2half_rn(v1);
                    __half h10 = __float2half_rn(LSCALE * (v0 - __half2float(h00)));
                    __half h11 = __float2half_rn(LSCALE * (v1 - __half2float(h01)));
                    *(__half2*)&O0[(size_t)grow * ldc + gcol] = __halves2half2(h00, h01);
                    *(__half2*)&O1[(size_t)grow * ldc + gcol] = __halves2half2(h10, h11);
                } else {
                    float2 v; v.x = v0; v.y = v1;
                    *(float2*)&outf[(size_t)grow * ldc + gcol] = v;
                }
            }
        }
}

// ---------------------------------------------------------------------------
// counter reset (graph replays must be deterministic)
// ---------------------------------------------------------------------------
__global__ void k_reset() { if (threadIdx.x == 0) g_devCount = 0; }

// ---------------------------------------------------------------------------
// exact mem1 recursion for flagged elements; record deviation vs s_t*cur1
// ---------------------------------------------------------------------------
__global__ void k_fixup()
{
    const int i = blockIdx.x * blockDim.x + threadIdx.x;
    int cnt = g_devCount;
    if (cnt > MAXDEV) cnt = MAXDEV;
    if (i >= cnt) return;
    const float S[10] = S_LIST;
    const float c = g_devV[i];
    float m = 0.0f;
#pragma unroll
    for (int t = 0; t < 10; t++) {
        const float r = (m > 15.0f) ? 15.0f : 0.0f;
        m = 0.5f * m + c - r;
        g_devD[i * 10 + t] = m - S[t] * c;
    }
}

// ---------------------------------------------------------------------------
// mem2 recursion + outputs; sums the SPLITK partials of G deterministically
// ---------------------------------------------------------------------------
__global__ void k_out(const float* __restrict__ Gp, const float* __restrict__ b2,
                      const float* __restrict__ W2, float* __restrict__ out)
{
    const int idx = blockIdx.x * blockDim.x + threadIdx.x;
    if (idx >= B_ * NO) return;
    const int b = idx / NO;
    const int n = idx - b * NO;

    const size_t BNO = (size_t)B_ * NO;
    float g = Gp[idx];
#pragma unroll
    for (int s = 1; s < SPLITK; s++) g += Gp[s * BNO + idx];
    const float bias = b2[n];

    float fix[10];
#pragma unroll
    for (int t = 0; t < 10; t++) fix[t] = 0.0f;

    int cnt = g_devCount;
    if (cnt > 0) {                       // expected never taken
        if (cnt > MAXDEV) cnt = MAXDEV;
        for (int e = 0; e < cnt; e++) {
            if (g_devB[e] == b) {
                const float w = W2[(size_t)n * NH + g_devH[e]];
#pragma unroll
                for (int t = 0; t < 10; t++)
                    fix[t] = fmaf(g_devD[e * 10 + t], w, fix[t]);
            }
        }
    }

    const float S[10] = S_LIST;
    float m2 = 0.0f;
#pragma unroll
    for (int t = 0; t < 10; t++) {
        const float r  = (m2 > 10.0f) ? 10.0f : 0.0f;
        const float c2 = S[t] * g + bias + fix[t];
        m2 = 0.5f * m2 + c2 - r;
    }

    out[idx] = (m2 > 10.0f) ? 1.0f : 0.0f;      // spk2
    out[BNO + idx] = m2;                        // mem2
}

// ---------------------------------------------------------------------------
// launch
// ---------------------------------------------------------------------------
extern "C" void kernel_launch(void* const* d_in, const int* in_sizes, int n_in,
                              void* d_out, int out_size)
{
    const float* x  = (const float*)d_in[0];
    const float* W1 = (const float*)d_in[1];
    const float* b1 = (const float*)d_in[2];
    const float* W2 = (const float*)d_in[3];
    const float* b2 = (const float*)d_in[4];
    float* out = (float*)d_out;

    void *p;
    cudaGetSymbolAddress(&p, g_xh0);  __half* xh0  = (__half*)p;
    cudaGetSymbolAddress(&p, g_xh1);  __half* xh1  = (__half*)p;
    cudaGetSymbolAddress(&p, g_w1h0); __half* w1h0 = (__half*)p;
    cudaGetSymbolAddress(&p, g_w1h1); __half* w1h1 = (__half*)p;
    cudaGetSymbolAddress(&p, g_w2h0); __half* w2h0 = (__half*)p;
    cudaGetSymbolAddress(&p, g_w2h1); __half* w2h1 = (__half*)p;
    cudaGetSymbolAddress(&p, g_c1h0); __half* c1h0 = (__half*)p;
    cudaGetSymbolAddress(&p, g_c1h1); __half* c1h1 = (__half*)p;
    cudaGetSymbolAddress(&p, g_Gpv);  float*  Gp   = (float*)p;

    cudaFuncSetAttribute(gemm_h2<0>, cudaFuncAttributeMaxDynamicSharedMemorySize, SM_BYTES);
    cudaFuncSetAttribute(gemm_h2<1>, cudaFuncAttributeMaxDynamicSharedMemorySize, SM_BYTES);

    k_reset<<<1, 32>>>();

    // fp16 splits (lo scaled by 2048); weights pre-scaled by exact powers of 2
    k_split<<<(B_ * NI / 4) / 256, 256>>>(x,  xh0,  xh1,  1.0f,  B_ * NI / 4);
    k_split<<<(NH * NI / 4) / 256, 256>>>(W1, w1h0, w1h1, 32.0f, NH * NI / 4);
    k_split<<<(NO * NH / 4) / 256, 256>>>(W2, w2h0, w2h1, 64.0f, NO * NH / 4);

    // cur1 = x @ W1^T + b1 : (acc + cor/2048)/32 + b1, detect, write split
    {
        dim3 grid(NH / BN, B_ / BM, 1);
        gemm_h2<0><<<grid, 256, SM_BYTES>>>(xh0, xh1, w1h0, w1h1, b1,
                                            c1h0, c1h1, nullptr,
                                            NI, NI, NH, NI, 1.0f / 32.0f);
    }

    k_fixup<<<MAXDEV / 128, 128>>>();

    // G partials = cur1 @ W2^T : (acc + cor/2048)/64, split-K=4 over K=NH
    {
        dim3 grid(NO / BN, B_ / BM, SPLITK);
        gemm_h2<1><<<grid, 256, SM_BYTES>>>(c1h0, c1h1, w2h0, w2h1, nullptr,
                                            nullptr, nullptr, Gp,
                                            NH, NH, NO, NH / SPLITK, 1.0f / 64.0f);
    }

    // mem2 scan + outputs
    k_out<<<(B_ * NO) / 256, 256>>>(Gp, b2, W2, out);
}

// round 12
// speedup vs baseline: 2.3576x; 1.0135x over previous
#include <cuda_runtime.h>
#include <cuda_fp16.h>
#include <cstdint>

// Problem constants (fixed by reference setup_inputs)
#define B_   4096
#define NI   1024
#define NH   4096
#define NO   512
#define MAXDEV 1024
#define SPLITK 4
#define LSCALE 2048.0f           // Ootomo residual up-scale (exact power of 2)
#define INV_LSCALE (1.0f / 2048.0f)

// ---------------------------------------------------------------------------
// Static scratch as float4 arrays (16B alignment for cp.async), cast to half*.
// Weight pre-scales (exact powers of 2) keep hi terms O(1):
//   W1*32 (W1~N(0,1/1024)), W2*64 (W2~N(0,1/4096)).
// All lo arrays store 2048*(v - fp16(v)) so they are NORMAL fp16 (~0.25|v|),
// immune to tensor-core FTZ of subnormal inputs (the round-8 failure).
// ---------------------------------------------------------------------------
__device__ float4 g_xh0[(size_t)B_ * NI / 8],  g_xh1[(size_t)B_ * NI / 8];
__device__ float4 g_w1h0[(size_t)NH * NI / 8], g_w1h1[(size_t)NH * NI / 8];
__device__ float4 g_w2h0[(size_t)NO * NH / 8], g_w2h1[(size_t)NO * NH / 8];
__device__ float4 g_c1h0[(size_t)B_ * NH / 8], g_c1h1[(size_t)B_ * NH / 8];
__device__ float4 g_Gpv[(size_t)SPLITK * B_ * NO / 4];
__device__ int    g_devCount;
__device__ int    g_devB[MAXDEV];
__device__ int    g_devH[MAXDEV];
__device__ float  g_devV[MAXDEV];
__device__ float  g_devD[MAXDEV * 10];

// s_t = sum_{i=0}^{t-1} 0.5^i (exact dyadic values)
#define S_LIST {1.0f, 1.5f, 1.75f, 1.875f, 1.9375f, 1.96875f, 1.984375f, \
                1.9921875f, 1.99609375f, 1.998046875f}

// ---------------------------------------------------------------------------
// PTX helpers (base sm_100 target: fp16 mma.sync + cp.async + ldmatrix)
// ---------------------------------------------------------------------------
__device__ __forceinline__ uint32_t smem_u32(const void* p) {
    uint32_t a;
    asm("{ .reg .u64 t; cvta.to.shared.u64 t, %1; cvt.u32.u64 %0, t; }" : "=r"(a) : "l"(p));
    return a;
}
__device__ __forceinline__ void cp16(uint32_t dst, const void* src) {
    asm volatile("cp.async.cg.shared.global [%0], [%1], 16;" :: "r"(dst), "l"(src) : "memory");
}
#define CP_COMMIT() asm volatile("cp.async.commit_group;" ::: "memory")
#define CP_WAIT0()  asm volatile("cp.async.wait_group 0;" ::: "memory")

// D(16x8,f32) += A(16x16,f16) @ B(16x8,f16)
__device__ __forceinline__ void mma16(float* d, const uint32_t* a, const uint32_t* b) {
    asm volatile(
        "mma.sync.aligned.m16n8k16.row.col.f32.f16.f16.f32 "
        "{%0,%1,%2,%3}, {%4,%5,%6,%7}, {%8,%9}, {%0,%1,%2,%3};"
        : "+f"(d[0]), "+f"(d[1]), "+f"(d[2]), "+f"(d[3])
        : "r"(a[0]), "r"(a[1]), "r"(a[2]), "r"(a[3]), "r"(b[0]), "r"(b[1]));
}

// 4x 8x8 b16 matrices, standard (non-transposed) distribution
__device__ __forceinline__ void ldsm4(uint32_t* r, uint32_t addr) {
    asm volatile("ldmatrix.sync.aligned.m8n8.x4.shared.b16 {%0,%1,%2,%3}, [%4];"
        : "=r"(r[0]), "=r"(r[1]), "=r"(r[2]), "=r"(r[3]) : "r"(addr));
}

// ---------------------------------------------------------------------------
// Elementwise split with pre-scale:
//   v = f*scale;  h0 = fp16(v);  h1 = fp16(2048*(v - h0))   (always normal)
// ---------------------------------------------------------------------------
__global__ void k_split(const float* __restrict__ s, __half* __restrict__ h0,
                        __half* __restrict__ h1, float scale, int n4)
{
    int i = blockIdx.x * blockDim.x + threadIdx.x;
    if (i >= n4) return;
    float4 v = ((const float4*)s)[i];
    v.x *= scale; v.y *= scale; v.z *= scale; v.w *= scale;
    __half a0 = __float2half_rn(v.x), a1 = __float2half_rn(v.y);
    __half a2 = __float2half_rn(v.z), a3 = __float2half_rn(v.w);
    __half b0 = __float2half_rn(LSCALE * (v.x - __half2float(a0)));
    __half b1 = __float2half_rn(LSCALE * (v.y - __half2float(a1)));
    __half b2 = __float2half_rn(LSCALE * (v.z - __half2float(a2)));
    __half b3 = __float2half_rn(LSCALE * (v.w - __half2float(a3)));
    ((__half2*)h0)[2 * i]     = __halves2half2(a0, a1);
    ((__half2*)h0)[2 * i + 1] = __halves2half2(a2, a3);
    ((__half2*)h1)[2 * i]     = __halves2half2(b0, b1);
    ((__half2*)h1)[2 * i + 1] = __halves2half2(b2, b3);
}

// ---------------------------------------------------------------------------
// fp16 split-GEMM with separate correction accumulator (Ootomo):
//   acc  += Ah@Bh ;  cor += Ah@Bl' + Al'@Bh ;  C = (acc + cor/2048) * inv
// CTA tile 128x128, BK=32, 8 warps (warp tile 32x64), 2-stage cp.async.
// Fragments loaded via ldmatrix.x4 (12 LDSM/slab vs 96 scalar LDS).
// Smem rows: 32 halfs padded to 20 words; 20i mod 32 is a bank permutation,
// so every ldmatrix (8 rows x 16B at 80B stride) is conflict-free.
// EPI=0: +bias, reset-detect, write fp16 split (hi, 2048*lo) of result
// EPI=1: write fp32 partial at blockIdx.z K-slice
// ---------------------------------------------------------------------------
#define BM 128
#define BN 128
#define BK 32
#define SW 20                          // words per row (16 data + 4 pad)
#define A_WORDS (BM * SW)              // 2560
#define B_WORDS (BN * SW)              // 2560
#define STGW (2 * A_WORDS + 2 * B_WORDS)  // 10240 words = 40960 B
#define SM_BYTES (2 * STGW * 4)        // 81920

template <int EPI>
__global__ __launch_bounds__(256, 1)
void gemm_h2(const __half* __restrict__ A0, const __half* __restrict__ A1,
             const __half* __restrict__ B0, const __half* __restrict__ B1,
             const float* __restrict__ bias,
             __half* __restrict__ O0, __half* __restrict__ O1,
             float* __restrict__ Of,
             int lda, int ldb, int ldc, int Klen, float inv)
{
    extern __shared__ uint32_t smw[];
    const uint32_t smb = smem_u32(smw);
    const int tid  = threadIdx.x;
    const int wid  = tid >> 5;
    const int lane = tid & 31;
    const int gr   = lane >> 2;   // fragment row group
    const int tg   = lane & 3;    // fragment col group
    const int warpRow = (wid >> 1) * 32;   // 4 warp-rows of 32
    const int warpCol = (wid & 1) * 64;    // 2 warp-cols of 64
    const int row0 = blockIdx.y * BM;
    const int col0 = blockIdx.x * BN;
    const int k0   = blockIdx.z * Klen;

    // ldmatrix lane addressing (word offsets within a stage):
    // A x4 matrix order {m0-7,k0-7},{m8-15,k0-7},{m0-7,k8-15},{m8-15,k8-15}
    const int arow = ((lane >> 3) & 1) * 8 + (lane & 7);
    const int achk = (lane >> 4) * 4;
    const int aBase = (warpRow + arow) * SW + achk;
    // B x4 covers an nf-pair: {n0-7,k0-7},{n0-7,k8-15},{n8-15,k0-7},{n8-15,k8-15}
    const int brow = ((lane >> 4) & 1) * 8 + (lane & 7);
    const int bchk = ((lane >> 3) & 1) * 4;
    const int bBase = (warpCol + brow) * SW + bchk;

    float acc[2][8][4];
    float cor[2][8][4];
#pragma unroll
    for (int mf = 0; mf < 2; mf++)
#pragma unroll
        for (int nf = 0; nf < 8; nf++)
#pragma unroll
            for (int j = 0; j < 4; j++) { acc[mf][nf][j] = 0.0f; cor[mf][nf][j] = 0.0f; }

    // stage loader: K-tile t -> buffer s (each row = 32 halfs = 4x cp16)
    auto load_stage = [&](int t, int s) {
        const int kof = k0 + t * BK;
        const uint32_t sa = smb + (uint32_t)(s * STGW) * 4;
        for (int q = tid; q < BM * 4; q += 256) {
            const int r = q >> 2, ch = q & 3;
            const size_t go = (size_t)(row0 + r) * lda + kof + ch * 8;
            const uint32_t so = sa + (uint32_t)(r * SW + ch * 4) * 4;
            cp16(so, A0 + go);
            cp16(so + A_WORDS * 4, A1 + go);
        }
        for (int q = tid; q < BN * 4; q += 256) {
            const int r = q >> 2, ch = q & 3;
            const size_t go = (size_t)(col0 + r) * ldb + kof + ch * 8;
            const uint32_t so = sa + (uint32_t)(2 * A_WORDS + r * SW + ch * 4) * 4;
            cp16(so, B0 + go);
            cp16(so + B_WORDS * 4, B1 + go);
        }
        CP_COMMIT();
    };

    const int T = Klen / BK;
    load_stage(0, 0);

    for (int t = 0; t < T; t++) {
        CP_WAIT0();            // stage t resident
        __syncthreads();
        if (t + 1 < T) load_stage(t + 1, (t + 1) & 1);   // overlaps compute below

        const uint32_t sa = smb + (uint32_t)((t & 1) * STGW) * 4;

#pragma unroll
        for (int sl = 0; sl < 2; sl++) {     // two k16 slabs per BK=32
            const int kb = sl * 8;           // word offset within row
            uint32_t ah[2][4], al[2][4];
#pragma unroll
            for (int mf = 0; mf < 2; mf++) {
                const uint32_t aoff = sa + (uint32_t)(aBase + mf * 16 * SW + kb) * 4;
                ldsm4(ah[mf], aoff);
                ldsm4(al[mf], aoff + A_WORDS * 4);
            }
#pragma unroll
            for (int p = 0; p < 4; p++) {    // nf pairs: nf = 2p, 2p+1
                const uint32_t boff = sa + (uint32_t)(2 * A_WORDS + bBase + p * 16 * SW + kb) * 4;
                uint32_t bh4[4], bl4[4];
                ldsm4(bh4, boff);
                ldsm4(bl4, boff + B_WORDS * 4);
#pragma unroll
                for (int half_ = 0; half_ < 2; half_++) {
                    const int nf = 2 * p + half_;
                    const uint32_t* bh = bh4 + 2 * half_;
                    const uint32_t* bl = bl4 + 2 * half_;
#pragma unroll
                    for (int mf = 0; mf < 2; mf++) {
                        mma16(acc[mf][nf], ah[mf], bh);   // hi*hi   -> main
                        mma16(cor[mf][nf], ah[mf], bl);   // hi*lo'  -> corr (2048x)
                        mma16(cor[mf][nf], al[mf], bh);   // lo'*hi  -> corr (2048x)
                    }
                }
            }
        }
        __syncthreads();
    }

    // epilogue: c0,c1 -> row gr, cols 2tg..2tg+1; c2,c3 -> row gr+8
    float* outf = Of;
    if (EPI == 1) outf += (size_t)blockIdx.z * B_ * NO;

#pragma unroll
    for (int mf = 0; mf < 2; mf++)
#pragma unroll
        for (int h = 0; h < 2; h++) {
            const int grow = row0 + warpRow + mf * 16 + gr + h * 8;
#pragma unroll
            for (int nf = 0; nf < 8; nf++) {
                const int gcol = col0 + warpCol + nf * 8 + tg * 2;
                float v0 = fmaf(cor[mf][nf][h * 2 + 0], INV_LSCALE, acc[mf][nf][h * 2 + 0]) * inv;
                float v1 = fmaf(cor[mf][nf][h * 2 + 1], INV_LSCALE, acc[mf][nf][h * 2 + 1]) * inv;
                if (EPI == 0) {
                    v0 += __ldg(&bias[gcol]);
                    v1 += __ldg(&bias[gcol + 1]);
                    // mem1 can only reset if cur1 > 15/1.996 = 7.51; use 7.5
                    if (v0 > 7.5f) {
                        int p = atomicAdd(&g_devCount, 1);
                        if (p < MAXDEV) { g_devB[p] = grow; g_devH[p] = gcol; g_devV[p] = v0; }
                    }
                    if (v1 > 7.5f) {
                        int p = atomicAdd(&g_devCount, 1);
                        if (p < MAXDEV) { g_devB[p] = grow; g_devH[p] = gcol + 1; g_devV[p] = v1; }
                    }
                    __half h00 = __float2half_rn(v0), h01 = __float2half_rn(v1);
                    __half h10 = __float2half_rn(LSCALE * (v0 - __half2float(h00)));
                    __half h11 = __float2half_rn(LSCALE * (v1 - __half2float(h01)));
                    *(__half2*)&O0[(size_t)grow * ldc + gcol] = __halves2half2(h00, h01);
                    *(__half2*)&O1[(size_t)grow * ldc + gcol] = __halves2half2(h10, h11);
                } else {
                    float2 v; v.x = v0; v.y = v1;
                    *(float2*)&outf[(size_t)grow * ldc + gcol] = v;
                }
            }
        }
}

// ---------------------------------------------------------------------------
// counter reset (graph replays must be deterministic)
// ---------------------------------------------------------------------------
__global__ void k_reset() { if (threadIdx.x == 0) g_devCount = 0; }

// ---------------------------------------------------------------------------
// exact mem1 recursion for flagged elements; record deviation vs s_t*cur1
// ---------------------------------------------------------------------------
__global__ void k_fixup()
{
    const int i = blockIdx.x * blockDim.x + threadIdx.x;
    int cnt = g_devCount;
    if (cnt > MAXDEV) cnt = MAXDEV;
    if (i >= cnt) return;
    const float S[10] = S_LIST;
    const float c = g_devV[i];
    float m = 0.0f;
#pragma unroll
    for (int t = 0; t < 10; t++) {
        const float r = (m > 15.0f) ? 15.0f : 0.0f;
        m = 0.5f * m + c - r;
        g_devD[i * 10 + t] = m - S[t] * c;
    }
}

// ---------------------------------------------------------------------------
// mem2 recursion + outputs; sums the SPLITK partials of G deterministically
// ---------------------------------------------------------------------------
__global__ void k_out(const float* __restrict__ Gp, const float* __restrict__ b2,
                      const float* __restrict__ W2, float* __restrict__ out)
{
    const int idx = blockIdx.x * blockDim.x + threadIdx.x;
    if (idx >= B_ * NO) return;
    const int b = idx / NO;
    const int n = idx - b * NO;

    const size_t BNO = (size_t)B_ * NO;
    float g = Gp[idx];
#pragma unroll
    for (int s = 1; s < SPLITK; s++) g += Gp[s * BNO + idx];
    const float bias = b2[n];

    float fix[10];
#pragma unroll
    for (int t = 0; t < 10; t++) fix[t] = 0.0f;

    int cnt = g_devCount;
    if (cnt > 0) {                       // expected never taken
        if (cnt > MAXDEV) cnt = MAXDEV;
        for (int e = 0; e < cnt; e++) {
            if (g_devB[e] == b) {
                const float w = W2[(size_t)n * NH + g_devH[e]];
#pragma unroll
                for (int t = 0; t < 10; t++)
                    fix[t] = fmaf(g_devD[e * 10 + t], w, fix[t]);
            }
        }
    }

    const float S[10] = S_LIST;
    float m2 = 0.0f;
#pragma unroll
    for (int t = 0; t < 10; t++) {
        const float r  = (m2 > 10.0f) ? 10.0f : 0.0f;
        const float c2 = S[t] * g + bias + fix[t];
        m2 = 0.5f * m2 + c2 - r;
    }

    out[idx] = (m2 > 10.0f) ? 1.0f : 0.0f;      // spk2
    out[BNO + idx] = m2;                        // mem2
}

// ---------------------------------------------------------------------------
// launch
// ---------------------------------------------------------------------------
extern "C" void kernel_launch(void* const* d_in, const int* in_sizes, int n_in,
                              void* d_out, int out_size)
{
    const float* x  = (const float*)d_in[0];
    const float* W1 = (const float*)d_in[1];
    const float* b1 = (const float*)d_in[2];
    const float* W2 = (const float*)d_in[3];
    const float* b2 = (const float*)d_in[4];
    float* out = (float*)d_out;

    void *p;
    cudaGetSymbolAddress(&p, g_xh0);  __half* xh0  = (__half*)p;
    cudaGetSymbolAddress(&p, g_xh1);  __half* xh1  = (__half*)p;
    cudaGetSymbolAddress(&p, g_w1h0); __half* w1h0 = (__half*)p;
    cudaGetSymbolAddress(&p, g_w1h1); __half* w1h1 = (__half*)p;
    cudaGetSymbolAddress(&p, g_w2h0); __half* w2h0 = (__half*)p;
    cudaGetSymbolAddress(&p, g_w2h1); __half* w2h1 = (__half*)p;
    cudaGetSymbolAddress(&p, g_c1h0); __half* c1h0 = (__half*)p;
    cudaGetSymbolAddress(&p, g_c1h1); __half* c1h1 = (__half*)p;
    cudaGetSymbolAddress(&p, g_Gpv);  float*  Gp   = (float*)p;

    cudaFuncSetAttribute(gemm_h2<0>, cudaFuncAttributeMaxDynamicSharedMemorySize, SM_BYTES);
    cudaFuncSetAttribute(gemm_h2<1>, cudaFuncAttributeMaxDynamicSharedMemorySize, SM_BYTES);

    k_reset<<<1, 32>>>();

    // fp16 splits (lo scaled by 2048); weights pre-scaled by exact powers of 2
    k_split<<<(B_ * NI / 4) / 256, 256>>>(x,  xh0,  xh1,  1.0f,  B_ * NI / 4);
    k_split<<<(NH * NI / 4) / 256, 256>>>(W1, w1h0, w1h1, 32.0f, NH * NI / 4);
    k_split<<<(NO * NH / 4) / 256, 256>>>(W2, w2h0, w2h1, 64.0f, NO * NH / 4);

    // cur1 = x @ W1^T + b1 : (acc + cor/2048)/32 + b1, detect, write split
    {
        dim3 grid(NH / BN, B_ / BM, 1);
        gemm_h2<0><<<grid, 256, SM_BYTES>>>(xh0, xh1, w1h0, w1h1, b1,
                                            c1h0, c1h1, nullptr,
                                            NI, NI, NH, NI, 1.0f / 32.0f);
    }

    k_fixup<<<MAXDEV / 128, 128>>>();

    // G partials = cur1 @ W2^T : (acc + cor/2048)/64, split-K=4 over K=NH
    {
        dim3 grid(NO / BN, B_ / BM, SPLITK);
        gemm_h2<1><<<grid, 256, SM_BYTES>>>(c1h0, c1h1, w2h0, w2h1, nullptr,
                                            nullptr, nullptr, Gp,
                                            NH, NH, NO, NH / SPLITK, 1.0f / 64.0f);
    }

    // mem2 scan + outputs
    k_out<<<(B_ * NO) / 256, 256>>>(Gp, b2, W2, out);
}

// round 14
// speedup vs baseline: 5.0296x; 2.1333x over previous
#include <cuda_runtime.h>
#include <cuda_fp16.h>
#include <cstdint>

// Problem constants (fixed by reference setup_inputs)
#define B_   4096
#define NI   1024
#define NH   4096
#define NO   512
#define MAXDEV 1024
#define SK1  8                   // split-K for W21 = W2@W1 (K=NH)
#define SK2  2                   // split-K for G = x@W21^T (K=NI)
#define LSCALE 2048.0f           // Ootomo residual up-scale (exact power of 2)
#define INV_LSCALE (1.0f / 2048.0f)
#define DETECT_THR 7.35f         // hh-only error ~6.5e-3 << margin to 7.5147

// ---------------------------------------------------------------------------
// Static scratch as float4 arrays (16B alignment for cp.async), cast at use.
// Scales (exact powers of 2): x*1, W1*32, W2*64, W21*32 -> hi terms O(1).
// lo arrays hold 2048*(v - fp16(v)): always NORMAL fp16 (no tensor-core FTZ).
// ---------------------------------------------------------------------------
__device__ float4 g_xh0v[(size_t)B_ * NI / 8],  g_xh1v[(size_t)B_ * NI / 8];
__device__ float4 g_w1h0v[(size_t)NH * NI / 8];                  // detect B (hh only)
__device__ float4 g_w1t0v[(size_t)NI * NH / 8], g_w1t1v[(size_t)NI * NH / 8]; // W1^T splits
__device__ float4 g_w2h0v[(size_t)NO * NH / 8], g_w2h1v[(size_t)NO * NH / 8];
__device__ float4 g_w21h0v[(size_t)NO * NI / 8], g_w21h1v[(size_t)NO * NI / 8];
__device__ float4 g_Wpv[(size_t)SK1 * NO * NI / 4];   // W21 partials (fp32)
__device__ float4 g_Gpv[(size_t)SK2 * B_ * NO / 4];   // G partials (fp32)
__device__ float  g_gvec[NO];                         // W2 @ b1
__device__ int    g_devCount;
__device__ int    g_devB[MAXDEV];
__device__ int    g_devH[MAXDEV];
__device__ float  g_devD[MAXDEV * 10];

// s_t = sum_{i=0}^{t-1} 0.5^i (exact dyadic values)
#define S_LIST {1.0f, 1.5f, 1.75f, 1.875f, 1.9375f, 1.96875f, 1.984375f, \
                1.9921875f, 1.99609375f, 1.998046875f}

// ---------------------------------------------------------------------------
// PTX helpers (base sm_100 target: fp16 mma.sync + cp.async + ldmatrix)
// ---------------------------------------------------------------------------
__device__ __forceinline__ uint32_t smem_u32(const void* p) {
    uint32_t a;
    asm("{ .reg .u64 t; cvta.to.shared.u64 t, %1; cvt.u32.u64 %0, t; }" : "=r"(a) : "l"(p));
    return a;
}
__device__ __forceinline__ void cp16(uint32_t dst, const void* src) {
    asm volatile("cp.async.cg.shared.global [%0], [%1], 16;" :: "r"(dst), "l"(src) : "memory");
}
#define CP_COMMIT() asm volatile("cp.async.commit_group;" ::: "memory")
#define CP_WAIT0()  asm volatile("cp.async.wait_group 0;" ::: "memory")

// D(16x8,f32) += A(16x16,f16) @ B(16x8,f16)
__device__ __forceinline__ void mma16(float* d, const uint32_t* a, const uint32_t* b) {
    asm volatile(
        "mma.sync.aligned.m16n8k16.row.col.f32.f16.f16.f32 "
        "{%0,%1,%2,%3}, {%4,%5,%6,%7}, {%8,%9}, {%0,%1,%2,%3};"
        : "+f"(d[0]), "+f"(d[1]), "+f"(d[2]), "+f"(d[3])
        : "r"(a[0]), "r"(a[1]), "r"(a[2]), "r"(a[3]), "r"(b[0]), "r"(b[1]));
}
__device__ __forceinline__ void ldsm4(uint32_t* r, uint32_t addr) {
    asm volatile("ldmatrix.sync.aligned.m8n8.x4.shared.b16 {%0,%1,%2,%3}, [%4];"
        : "=r"(r[0]), "=r"(r[1]), "=r"(r[2]), "=r"(r[3]) : "r"(addr));
}

// ---------------------------------------------------------------------------
// Elementwise splits
// ---------------------------------------------------------------------------
__global__ void k_split(const float* __restrict__ s, __half* __restrict__ h0,
                        __half* __restrict__ h1, float scale, int n4)
{
    int i = blockIdx.x * blockDim.x + threadIdx.x;
    if (i >= n4) return;
    float4 v = ((const float4*)s)[i];
    v.x *= scale; v.y *= scale; v.z *= scale; v.w *= scale;
    __half a0 = __float2half_rn(v.x), a1 = __float2half_rn(v.y);
    __half a2 = __float2half_rn(v.z), a3 = __float2half_rn(v.w);
    __half b0 = __float2half_rn(LSCALE * (v.x - __half2float(a0)));
    __half b1 = __float2half_rn(LSCALE * (v.y - __half2float(a1)));
    __half b2 = __float2half_rn(LSCALE * (v.z - __half2float(a2)));
    __half b3 = __float2half_rn(LSCALE * (v.w - __half2float(a3)));
    ((__half2*)h0)[2 * i]     = __halves2half2(a0, a1);
    ((__half2*)h0)[2 * i + 1] = __halves2half2(a2, a3);
    ((__half2*)h1)[2 * i]     = __halves2half2(b0, b1);
    ((__half2*)h1)[2 * i + 1] = __halves2half2(b2, b3);
}

// hi-only split (for the detect GEMM's W1 operand)
__global__ void k_split1(const float* __restrict__ s, __half* __restrict__ h0,
                         float scale, int n4)
{
    int i = blockIdx.x * blockDim.x + threadIdx.x;
    if (i >= n4) return;
    float4 v = ((const float4*)s)[i];
    ((__half2*)h0)[2 * i]     = __halves2half2(__float2half_rn(v.x * scale),
                                               __float2half_rn(v.y * scale));
    ((__half2*)h0)[2 * i + 1] = __halves2half2(__float2half_rn(v.z * scale),
                                               __float2half_rn(v.w * scale));
}

// Transpose + split: W1 [NH,NI] fp32 -> w1t hi/lo [NI,NH] fp16, scale 32
__global__ void k_tsplit(const float* __restrict__ W1, __half* __restrict__ t0,
                         __half* __restrict__ t1)
{
    __shared__ float sm[32][33];
    const int tx = threadIdx.x & 31, ty = threadIdx.x >> 5;   // 32x8
    const int bn = blockIdx.x;    // NI/32
    const int bh = blockIdx.y;    // NH/32
#pragma unroll
    for (int i = 0; i < 4; i++) {
        int r = ty + 8 * i;
        sm[r][tx] = W1[(size_t)(bh * 32 + r) * NI + bn * 32 + tx];
    }
    __syncthreads();
#pragma unroll
    for (int i = 0; i < 4; i++) {
        int r = ty + 8 * i;                       // local ni row
        float v = 32.0f * sm[tx][r];              // out(ni, nh) = W1[nh][ni]
        __half h0 = __float2half_rn(v);
        __half h1 = __float2half_rn(LSCALE * (v - __half2float(h0)));
        size_t o = (size_t)(bn * 32 + r) * NH + bh * 32 + tx;
        t0[o] = h0; t1[o] = h1;
    }
}

// ---------------------------------------------------------------------------
// fp16 split-GEMM (Ootomo): C[M,N] = A[M,K] @ B[N,K]^T
// CTA 128x128, BK=32, 8 warps (32x64 warp tile), 2-stage cp.async, ldmatrix.
// EPI=0: hh-only DETECT (no output; flag acc*inv + bias > DETECT_THR)
// EPI=1: 3-term (acc + cor/2048)*inv -> fp32 partial at z slice (zStride)
// Smem rows padded to SW=20 words: 20i mod 32 is a bank permutation.
// ---------------------------------------------------------------------------
#define BM 128
#define BN 128
#define BK 32
#define SW 20
#define A_WORDS (BM * SW)              // 2560
#define B_WORDS (BN * SW)              // 2560

template <int EPI>
__global__ __launch_bounds__(256, (EPI == 0) ? 2 : 1)
void gemm_h2(const __half* __restrict__ A0, const __half* __restrict__ A1,
             const __half* __restrict__ B0, const __half* __restrict__ B1,
             const float* __restrict__ bias, float* __restrict__ Of,
             int lda, int ldb, int ldc, int Klen, float inv, size_t zStride)
{
    constexpr int STGW = (EPI == 0) ? (A_WORDS + B_WORDS) : (2 * A_WORDS + 2 * B_WORDS);
    constexpr int OFFB = (EPI == 0) ? A_WORDS : 2 * A_WORDS;

    extern __shared__ uint32_t smw[];
    const uint32_t smb = smem_u32(smw);
    const int tid  = threadIdx.x;
    const int wid  = tid >> 5;
    const int lane = tid & 31;
    const int gr   = lane >> 2;
    const int tg   = lane & 3;
    const int warpRow = (wid >> 1) * 32;
    const int warpCol = (wid & 1) * 64;
    const int row0 = blockIdx.y * BM;
    const int col0 = blockIdx.x * BN;
    const int k0   = blockIdx.z * Klen;

    // ldmatrix lane addressing (word offsets within a stage)
    const int arow = ((lane >> 3) & 1) * 8 + (lane & 7);
    const int achk = (lane >> 4) * 4;
    const int aBase = (warpRow + arow) * SW + achk;
    const int brow = ((lane >> 4) & 1) * 8 + (lane & 7);
    const int bchk = ((lane >> 3) & 1) * 4;
    const int bBase = (warpCol + brow) * SW + bchk;

    float acc[2][8][4];
    float cor[2][8][4];
#pragma unroll
    for (int mf = 0; mf < 2; mf++)
#pragma unroll
        for (int nf = 0; nf < 8; nf++)
#pragma unroll
            for (int j = 0; j < 4; j++) { acc[mf][nf][j] = 0.0f; if (EPI == 1) cor[mf][nf][j] = 0.0f; }

    auto load_stage = [&](int t, int s) {
        const int kof = k0 + t * BK;
        const uint32_t sa = smb + (uint32_t)(s * STGW) * 4;
        for (int q = tid; q < BM * 4; q += 256) {
            const int r = q >> 2, ch = q & 3;
            const size_t go = (size_t)(row0 + r) * lda + kof + ch * 8;
            const uint32_t so = sa + (uint32_t)(r * SW + ch * 4) * 4;
            cp16(so, A0 + go);
            if (EPI == 1) cp16(so + A_WORDS * 4, A1 + go);
        }
        for (int q = tid; q < BN * 4; q += 256) {
            const int r = q >> 2, ch = q & 3;
            const size_t go = (size_t)(col0 + r) * ldb + kof + ch * 8;
            const uint32_t so = sa + (uint32_t)(OFFB + r * SW + ch * 4) * 4;
            cp16(so, B0 + go);
            if (EPI == 1) cp16(so + B_WORDS * 4, B1 + go);
        }
        CP_COMMIT();
    };

    const int T = Klen / BK;
    load_stage(0, 0);

    for (int t = 0; t < T; t++) {
        CP_WAIT0();
        __syncthreads();
        if (t + 1 < T) load_stage(t + 1, (t + 1) & 1);

        const uint32_t sa = smb + (uint32_t)((t & 1) * STGW) * 4;

#pragma unroll
        for (int sl = 0; sl < 2; sl++) {
            const int kb = sl * 8;
            uint32_t ah[2][4], al[2][4];
#pragma unroll
            for (int mf = 0; mf < 2; mf++) {
                const uint32_t aoff = sa + (uint32_t)(aBase + mf * 16 * SW + kb) * 4;
                ldsm4(ah[mf], aoff);
                if (EPI == 1) ldsm4(al[mf], aoff + A_WORDS * 4);
            }
#pragma unroll
            for (int p = 0; p < 4; p++) {
                const uint32_t boff = sa + (uint32_t)(OFFB + bBase + p * 16 * SW + kb) * 4;
                uint32_t bh4[4], bl4[4];
                ldsm4(bh4, boff);
                if (EPI == 1) ldsm4(bl4, boff + B_WORDS * 4);
#pragma unroll
                for (int half_ = 0; half_ < 2; half_++) {
                    const int nf = 2 * p + half_;
                    const uint32_t* bh = bh4 + 2 * half_;
#pragma unroll
                    for (int mf = 0; mf < 2; mf++) {
                        mma16(acc[mf][nf], ah[mf], bh);
                        if (EPI == 1) {
                            mma16(cor[mf][nf], ah[mf], bl4 + 2 * half_);
                            mma16(cor[mf][nf], al[mf], bh);
                        }
                    }
                }
            }
        }
        __syncthreads();
    }

    float* outf = Of + (size_t)blockIdx.z * zStride;

#pragma unroll
    for (int mf = 0; mf < 2; mf++)
#pragma unroll
        for (int h = 0; h < 2; h++) {
            const int grow = row0 + warpRow + mf * 16 + gr + h * 8;
#pragma unroll
            for (int nf = 0; nf < 8; nf++) {
                const int gcol = col0 + warpCol + nf * 8 + tg * 2;
                if (EPI == 0) {
                    float v0 = acc[mf][nf][h * 2 + 0] * inv + __ldg(&bias[gcol]);
                    float v1 = acc[mf][nf][h * 2 + 1] * inv + __ldg(&bias[gcol + 1]);
                    if (v0 > DETECT_THR) {
                        int p = atomicAdd(&g_devCount, 1);
                        if (p < MAXDEV) { g_devB[p] = grow; g_devH[p] = gcol; }
                    }
                    if (v1 > DETECT_THR) {
                        int p = atomicAdd(&g_devCount, 1);
                        if (p < MAXDEV) { g_devB[p] = grow; g_devH[p] = gcol + 1; }
                    }
                } else {
                    float2 v;
                    v.x = fmaf(cor[mf][nf][h * 2 + 0], INV_LSCALE, acc[mf][nf][h * 2 + 0]) * inv;
                    v.y = fmaf(cor[mf][nf][h * 2 + 1], INV_LSCALE, acc[mf][nf][h * 2 + 1]) * inv;
                    *(float2*)&outf[(size_t)grow * ldc + gcol] = v;
                }
            }
        }
}

// ---------------------------------------------------------------------------
// counter reset (graph replays must be deterministic)
// ---------------------------------------------------------------------------
__global__ void k_reset() { if (threadIdx.x == 0) g_devCount = 0; }

// ---------------------------------------------------------------------------
// W21 partial reduce + split (scale: partials = 2048*W21; want 32*W21 = /64)
// ---------------------------------------------------------------------------
__global__ void k_redsplit(const float* __restrict__ Wp, __half* __restrict__ h0o,
                           __half* __restrict__ h1o)
{
    int i = blockIdx.x * blockDim.x + threadIdx.x;
    if (i >= NO * NI) return;
    float s = 0.0f;
#pragma unroll
    for (int z = 0; z < SK1; z++) s += Wp[(size_t)z * NO * NI + i];
    s *= (1.0f / 64.0f);
    __half h0 = __float2half_rn(s);
    h0o[i] = h0;
    h1o[i] = __float2half_rn(LSCALE * (s - __half2float(h0)));
}

// ---------------------------------------------------------------------------
// gvec = W2 @ b1  (one warp per output)
// ---------------------------------------------------------------------------
__global__ void k_gvec(const float* __restrict__ W2, const float* __restrict__ b1)
{
    int w = (blockIdx.x * blockDim.x + threadIdx.x) >> 5;
    int lane = threadIdx.x & 31;
    if (w >= NO) return;
    float s = 0.0f;
    for (int k = lane; k < NH; k += 32) s = fmaf(W2[(size_t)w * NH + k], b1[k], s);
#pragma unroll
    for (int o = 16; o; o >>= 1) s += __shfl_xor_sync(0xFFFFFFFF, s, o);
    if (lane == 0) g_gvec[w] = s;
}

// ---------------------------------------------------------------------------
// exact fixup: recompute cur1 in fp32 for flagged elements, run exact mem1
// recursion, record deviation d_t = mem1(t) - s_t*cur1 (0 when no reset)
// ---------------------------------------------------------------------------
__global__ void k_fixup(const float* __restrict__ x, const float* __restrict__ W1,
                        const float* __restrict__ b1)
{
    const int i = blockIdx.x * blockDim.x + threadIdx.x;
    int cnt = g_devCount;
    if (cnt > MAXDEV) cnt = MAXDEV;
    if (i >= cnt) return;
    const int b = g_devB[i], hh = g_devH[i];
    float c = b1[hh];
    for (int k = 0; k < NI; k++)
        c = fmaf(x[(size_t)b * NI + k], W1[(size_t)hh * NI + k], c);
    const float S[10] = S_LIST;
    float m = 0.0f;
#pragma unroll
    for (int t = 0; t < 10; t++) {
        const float r = (m > 15.0f) ? 15.0f : 0.0f;
        m = 0.5f * m + c - r;
        g_devD[i * 10 + t] = m - S[t] * c;
    }
}

// ---------------------------------------------------------------------------
// mem2 recursion + outputs; g = sum of SK2 G-partials + gvec
// ---------------------------------------------------------------------------
__global__ void k_out(const float* __restrict__ Gp, const float* __restrict__ b2,
                      const float* __restrict__ W2, float* __restrict__ out)
{
    const int idx = blockIdx.x * blockDim.x + threadIdx.x;
    if (idx >= B_ * NO) return;
    const int b = idx / NO;
    const int n = idx - b * NO;

    const size_t BNO = (size_t)B_ * NO;
    float g = Gp[idx];
#pragma unroll
    for (int s = 1; s < SK2; s++) g += Gp[s * BNO + idx];
    g += g_gvec[n];
    const float bias = b2[n];

    float fix[10];
#pragma unroll
    for (int t = 0; t < 10; t++) fix[t] = 0.0f;

    int cnt = g_devCount;
    if (cnt > 0) {                       // expected never taken
        if (cnt > MAXDEV) cnt = MAXDEV;
        for (int e = 0; e < cnt; e++) {
            if (g_devB[e] == b) {
                const float w = W2[(size_t)n * NH + g_devH[e]];
#pragma unroll
                for (int t = 0; t < 10; t++)
                    fix[t] = fmaf(g_devD[e * 10 + t], w, fix[t]);
            }
        }
    }

    const float S[10] = S_LIST;
    float m2 = 0.0f;
#pragma unroll
    for (int t = 0; t < 10; t++) {
        const float r  = (m2 > 10.0f) ? 10.0f : 0.0f;
        const float c2 = S[t] * g + bias + fix[t];
        m2 = 0.5f * m2 + c2 - r;
    }

    out[idx] = (m2 > 10.0f) ? 1.0f : 0.0f;      // spk2
    out[BNO + idx] = m2;                        // mem2
}

// ---------------------------------------------------------------------------
// launch
// ---------------------------------------------------------------------------
extern "C" void kernel_launch(void* const* d_in, const int* in_sizes, int n_in,
                              void* d_out, int out_size)
{
    const float* x  = (const float*)d_in[0];
    const float* W1 = (const float*)d_in[1];
    const float* b1 = (const float*)d_in[2];
    const float* W2 = (const float*)d_in[3];
    const float* b2 = (const float*)d_in[4];
    float* out = (float*)d_out;

    void *p;
    cudaGetSymbolAddress(&p, g_xh0v);   __half* xh0   = (__half*)p;
    cudaGetSymbolAddress(&p, g_xh1v);   __half* xh1   = (__half*)p;
    cudaGetSymbolAddress(&p, g_w1h0v);  __half* w1h0  = (__half*)p;
    cudaGetSymbolAddress(&p, g_w1t0v);  __half* w1t0  = (__half*)p;
    cudaGetSymbolAddress(&p, g_w1t1v);  __half* w1t1  = (__half*)p;
    cudaGetSymbolAddress(&p, g_w2h0v);  __half* w2h0  = (__half*)p;
    cudaGetSymbolAddress(&p, g_w2h1v);  __half* w2h1  = (__half*)p;
    cudaGetSymbolAddress(&p, g_w21h0v); __half* w21h0 = (__half*)p;
    cudaGetSymbolAddress(&p, g_w21h1v); __half* w21h1 = (__half*)p;
    cudaGetSymbolAddress(&p, g_Wpv);    float*  Wp    = (float*)p;
    cudaGetSymbolAddress(&p, g_Gpv);    float*  Gp    = (float*)p;

    const int SMB0 = 2 * (A_WORDS + B_WORDS) * 4;          // 40960
    const int SMB1 = 2 * (2 * A_WORDS + 2 * B_WORDS) * 4;  // 81920
    cudaFuncSetAttribute(gemm_h2<0>, cudaFuncAttributeMaxDynamicSharedMemorySize, SMB0);
    cudaFuncSetAttribute(gemm_h2<1>, cudaFuncAttributeMaxDynamicSharedMemorySize, SMB1);

    k_reset<<<1, 32>>>();

    // splits
    k_split <<<(B_ * NI / 4) / 256, 256>>>(x,  xh0, xh1, 1.0f,  B_ * NI / 4);
    k_split <<<(NO * NH / 4) / 256, 256>>>(W2, w2h0, w2h1, 64.0f, NO * NH / 4);
    k_split1<<<(NH * NI / 4) / 256, 256>>>(W1, w1h0, 32.0f, NH * NI / 4);
    k_tsplit<<<dim3(NI / 32, NH / 32), 256>>>(W1, w1t0, w1t1);

    // DETECT: cur1 = x @ W1^T + b1 (hh-only); flags only, no output
    {
        dim3 grid(NH / BN, B_ / BM, 1);
        gemm_h2<0><<<grid, 256, SMB0>>>(xh0, nullptr, w1h0, nullptr, b1,
                                        nullptr, NI, NI, 0, NI, 1.0f / 32.0f, 0);
    }
    k_fixup<<<MAXDEV / 128, 128>>>(x, W1, b1);

    // W21 partials = (64*W2) @ (32*W1^T)^T, split-K=8 over K=NH
    {
        dim3 grid(NI / BN, NO / BM, SK1);
        gemm_h2<1><<<grid, 256, SMB1>>>(w2h0, w2h1, w1t0, w1t1, nullptr,
                                        Wp, NH, NH, NI, NH / SK1, 1.0f,
                                        (size_t)NO * NI);
    }
    k_redsplit<<<(NO * NI) / 256, 256>>>(Wp, w21h0, w21h1);
    k_gvec<<<NO * 32 / 256, 256>>>(W2, b1);

    // G partials = x @ (32*W21)^T / 32, split-K=2 over K=NI
    {
        dim3 grid(NO / BN, B_ / BM, SK2);
        gemm_h2<1><<<grid, 256, SMB1>>>(xh0, xh1, w21h0, w21h1, nullptr,
                                        Gp, NI, NI, NO, NI / SK2, 1.0f / 32.0f,
                                        (size_t)B_ * NO);
    }

    // mem2 scan + outputs
    k_out<<<(B_ * NO) / 256, 256>>>(Gp, b2, W2, out);
}